// round 13
// baseline (speedup 1.0000x reference)
#include <cuda_runtime.h>
#include <cuda_bf16.h>
#include <math.h>

#define Bb 32
#define Ss 512
#define Hh 1024
#define Mm 8
#define NTOK (Bb * Ss)       // 16384
#define NSPAN (NTOK * Mm)    // 131072
#define TOPK 4915            // int(0.3 * B * S)
#define NBIN 65536
#define NCOARSE 1024         // coarse bins: key >> 22 (== fine chunk of 64)
#define TIE_CAP 16384

// ---------------- device scratch ----------------
__device__ float g_query[Hh];
__device__ float g_e[NTOK];
__device__ float g_f[NTOK];
__device__ unsigned int g_keys[NSPAN];
__device__ int   g_hist16[NBIN];
__device__ int   g_coarse[NCOARSE];
__device__ unsigned char g_gbits[NTOK];   // bit l of byte t: span (t,l) valid&&gold
__device__ float g_sp_sum;
__device__ int   g_gold_cnt;
__device__ int   g_valid_cnt;
__device__ int   g_right;
__device__ int   g_tiecnt;
__device__ int   g_done;
__device__ int   g_tie[TIE_CAP];

__device__ __forceinline__ float warpReduceF(float v) {
    #pragma unroll
    for (int o = 16; o; o >>= 1) v += __shfl_xor_sync(0xffffffffu, v, o);
    return v;
}
__device__ __forceinline__ int warpReduceI(int v) {
    #pragma unroll
    for (int o = 16; o; o >>= 1) v += __shfl_xor_sync(0xffffffffu, v, o);
    return v;
}

// ---------------- kernel 1: query = w_in @ term_weight + b_in; init state ----------------
__global__ void k_query(const float* __restrict__ w_in,
                        const float* __restrict__ tw,
                        const float* __restrict__ b_in) {
    cudaTriggerProgrammaticLaunchCompletion();
    int r = blockIdx.x;
    if (r == 0 && threadIdx.x == 0) {
        g_sp_sum = 0.0f; g_gold_cnt = 0; g_valid_cnt = 0;
        g_right = 0; g_tiecnt = 0; g_done = 0;
    }
    const float4* wr = reinterpret_cast<const float4*>(w_in + (size_t)r * Hh);
    const float4* t4 = reinterpret_cast<const float4*>(tw);
    int i = threadIdx.x;
    float4 a = wr[i];
    float4 b = t4[i];
    float acc = a.x * b.x + a.y * b.y + a.z * b.z + a.w * b.w;

    __shared__ float sh[8];
    float v = warpReduceF(acc);
    if ((threadIdx.x & 31) == 0) sh[threadIdx.x >> 5] = v;
    __syncthreads();
    if (threadIdx.x < 8) {
        float x = sh[threadIdx.x];
        #pragma unroll
        for (int o = 4; o; o >>= 1) x += __shfl_xor_sync(0xffu, x, o);
        if (threadIdx.x == 0) g_query[r] = x + b_in[r];
    }
}

// ---------------- kernel 2: e/f dot products; also zeroes both hists ----------------
__global__ void k_ef(const float* __restrict__ hidden,
                     const float* __restrict__ score_w) {
    cudaTriggerProgrammaticLaunchCompletion();
    __shared__ float shq[Hh];
    __shared__ float shw[Hh];
    // independent prologue (overlaps k_query under PDL)
    int gid = blockIdx.x * blockDim.x + threadIdx.x;
    if (gid < NBIN) g_hist16[gid] = 0;
    if (gid < NCOARSE) g_coarse[gid] = 0;
    for (int i = threadIdx.x; i < Hh; i += blockDim.x) shw[i] = score_w[i];
    cudaGridDependencySynchronize();
    for (int i = threadIdx.x; i < Hh; i += blockDim.x) shq[i] = g_query[i];
    __syncthreads();

    int warp = threadIdx.x >> 5, lane = threadIdx.x & 31;
    int t = blockIdx.x * 8 + warp;
    const float4* hp = reinterpret_cast<const float4*>(hidden + (size_t)t * Hh);
    float e = 0.0f, f = 0.0f;
    #pragma unroll
    for (int c = 0; c < 8; c++) {
        int j = c * 32 + lane;
        float4 h = hp[j];
        int k = j * 4;
        e += h.x * shq[k] + h.y * shq[k + 1] + h.z * shq[k + 2] + h.w * shq[k + 3];
        f += h.x * shw[k] + h.y * shw[k + 1] + h.z * shw[k + 2] + h.w * shw[k + 3];
    }
    e = warpReduceF(e);
    f = warpReduceF(f);
    if (lane == 0) { g_e[t] = e; g_f[t] = f; }
}

// ---------------- kernel 3: scores, keys, gold bits, loss accum, dual histogram ----------------
__global__ void k_scores(const float* __restrict__ score_b_p,
                         const int* __restrict__ seq_len,
                         const int* __restrict__ gold_mask) {
    cudaTriggerProgrammaticLaunchCompletion();
    int t = blockIdx.x * blockDim.x + threadIdx.x;
    float sp_local = 0.0f;
    int gold_local = 0, valid_local = 0;

    // independent prologue: pure-input loads (overlap with k_ef under PDL)
    int b = t >> 9, s = t & (Ss - 1);
    int L = seq_len[b];
    float sb = score_b_p[0];
    const int4* gm4 = reinterpret_cast<const int4*>(gold_mask + t * Mm);
    int4 gm0 = gm4[0], gm1 = gm4[1];
    int gm[8] = {gm0.x, gm0.y, gm0.z, gm0.w, gm1.x, gm1.y, gm1.z, gm1.w};

    cudaGridDependencySynchronize();   // wait for g_e/g_f + hist zeroing

    if (t < NTOK) {
        float m = -INFINITY, den = 0.0f, num = 0.0f;
        unsigned keys[8];
        unsigned char gb = 0;
        #pragma unroll
        for (int l = 0; l < Mm; l++) {
            int pos = s + l; if (pos > Ss - 1) pos = Ss - 1;
            float el = g_e[(b << 9) + pos];
            float fl = g_f[(b << 9) + pos];
            float mn = fmaxf(m, el);
            float sc = expf(m - mn);
            float we = expf(el - mn);
            den = den * sc + we;
            num = num * sc + we * fl;
            m = mn;
            float score = num / den + sb;

            unsigned key;
            if (s + l + 1 <= L) {
                unsigned u = __float_as_uint(score);
                key = u ^ ((u >> 31) ? 0xFFFFFFFFu : 0x80000000u);
                valid_local++;
                if (gm[l] == 0) {
                    gold_local++;
                    gb |= (unsigned char)(1u << l);
                    sp_local += fmaxf(-score, 0.0f) + log1pf(expf(-fabsf(score)));
                }
            } else {
                key = 0x007FFFFFu;  // flipped -inf
            }
            keys[l] = key;
            atomicAdd(&g_hist16[key >> 16], 1);
            atomicAdd(&g_coarse[key >> 22], 1);
        }
        uint4* kp = reinterpret_cast<uint4*>(g_keys + t * Mm);
        kp[0] = make_uint4(keys[0], keys[1], keys[2], keys[3]);
        kp[1] = make_uint4(keys[4], keys[5], keys[6], keys[7]);
        g_gbits[t] = gb;
    }

    __shared__ float shf[8];
    __shared__ int shg[8], shv[8];
    float sp = warpReduceF(sp_local);
    int gd = warpReduceI(gold_local);
    int vd = warpReduceI(valid_local);
    if ((threadIdx.x & 31) == 0) {
        int w = threadIdx.x >> 5;
        shf[w] = sp; shg[w] = gd; shv[w] = vd;
    }
    __syncthreads();
    if (threadIdx.x == 0) {
        float S1 = 0.0f; int S2 = 0, S3 = 0;
        #pragma unroll
        for (int w = 0; w < 8; w++) { S1 += shf[w]; S2 += shg[w]; S3 += shv[w]; }
        atomicAdd(&g_sp_sum, S1);
        atomicAdd(&g_gold_cnt, S2);
        atomicAdd(&g_valid_cnt, S3);
    }
}

// ---------------- kernel 4: redundant per-block scan of coarse hist -> P,rem; count; final ----
// 16 blocks x 1024 threads. Each thread handles one token (8 spans).
__global__ void __launch_bounds__(1024, 1)
k_scan_count_final(float* __restrict__ out) {
    __shared__ int sch[NCOARSE];
    __shared__ int s_bins[64];
    __shared__ int s_bc, s_above;
    __shared__ int shc[32];
    __shared__ bool s_last;

    cudaGridDependencySynchronize();         // needs k_scores' hists + keys + gbits
    int tid = threadIdx.x;
    // ---- redundant suffix scan of coarse histogram (parallel across blocks) ----
    int csum = g_coarse[tid];
    sch[tid] = csum;
    __syncthreads();
    for (int off = 1; off < NCOARSE; off <<= 1) {
        int v = (tid + off < NCOARSE) ? sch[tid + off] : 0;
        __syncthreads();
        sch[tid] += v;
        __syncthreads();
    }
    int incl = sch[tid];
    int above = incl - csum;
    if (above < TOPK && incl >= TOPK) { s_bc = tid; s_above = above; }
    __syncthreads();
    int bc = s_bc;
    if (tid < 64) s_bins[tid] = g_hist16[bc * 64 + tid];   // fine bins of boundary coarse bin
    __syncthreads();
    if (tid == 0) {
        int cum = s_above;
        for (int bn = 63; bn >= 0; bn--) {
            int c = s_bins[bn];
            if (cum + c >= TOPK) {
                s_bc = bc * 64 + bn;        // P (16-bit prefix)
                s_above = TOPK - cum;       // rem
                break;
            }
            cum += c;
        }
    }
    __syncthreads();
    unsigned P = (unsigned)s_bc;
    int rem = s_above;

    // ---- vectorized count: token tg = gid (16*1024=16384 == NTOK) ----
    int tg = blockIdx.x * 1024 + tid;
    int gg = 0;
    {
        unsigned gb = g_gbits[tg];
        const uint4* kp = reinterpret_cast<const uint4*>(g_keys + tg * Mm);
        uint4 k0 = kp[0], k1 = kp[1];
        unsigned kk[8] = {k0.x, k0.y, k0.z, k0.w, k1.x, k1.y, k1.z, k1.w};
        #pragma unroll
        for (int l = 0; l < 8; l++) {
            unsigned top = kk[l] >> 16;
            if (top > P) {
                gg += (gb >> l) & 1;
            } else if (top == P) {
                int pos = atomicAdd(&g_tiecnt, 1);
                if (pos < TIE_CAP) g_tie[pos] = tg * Mm + l;
            }
        }
    }
    gg = warpReduceI(gg);
    if ((tid & 31) == 0) shc[tid >> 5] = gg;
    __syncthreads();
    if (tid == 0) {
        int S = 0;
        #pragma unroll
        for (int w = 0; w < 32; w++) S += shc[w];
        if (S) atomicAdd(&g_right, S);
        __threadfence();
        int d = atomicAdd(&g_done, 1);
        s_last = (d == (int)gridDim.x - 1);
    }
    __syncthreads();
    if (!s_last) return;

    // ---- final phase: only last block ----
    int n = g_tiecnt; if (n > TIE_CAP) n = TIE_CAP;
    __shared__ int s_g;
    if (tid == 0) s_g = 0;
    __syncthreads();

    int gtie = 0;
    for (int j = tid; j < n; j += 1024) {
        int ij = g_tie[j];
        unsigned kj = g_keys[ij];
        int rank = 0;
        for (int q = 0; q < n; q++) {
            int iq = g_tie[q];
            unsigned kq = g_keys[iq];
            if (kq > kj || (kq == kj && iq < ij)) rank++;
        }
        if (rank < rem) {
            if ((g_gbits[ij >> 3] >> (ij & 7)) & 1) gtie++;
        }
    }
    gtie = warpReduceI(gtie);
    if ((tid & 31) == 0 && gtie) atomicAdd(&s_g, gtie);
    __syncthreads();

    if (tid == 0) {
        int right = g_right + s_g;
        float nv = (float)g_valid_cnt;
        float loss = (g_sp_sum + 0.6931471805599453f * (float)(g_valid_cnt - g_gold_cnt)) / nv;
        out[0] = loss;
        out[1] = (float)right / (float)TOPK;
    }
}

// ---------------- launch (PDL on all dependent nodes) ----------------
extern "C" void kernel_launch(void* const* d_in, const int* in_sizes, int n_in,
                              void* d_out, int out_size) {
    const float* hidden  = (const float*)d_in[0];
    const float* tw      = (const float*)d_in[1];
    const float* w_in    = (const float*)d_in[2];
    const float* b_in    = (const float*)d_in[3];
    const float* score_w = (const float*)d_in[4];
    const float* score_b = (const float*)d_in[5];
    const int*   seq_len = (const int*)d_in[6];
    const int*   gold    = (const int*)d_in[7];
    float* out = (float*)d_out;

    cudaLaunchAttribute at[1];
    at[0].id = cudaLaunchAttributeProgrammaticStreamSerialization;
    at[0].val.programmaticStreamSerializationAllowed = 1;

    k_query<<<Hh, 256>>>(w_in, tw, b_in);
    {
        cudaLaunchConfig_t cfg = {};
        cfg.gridDim = dim3(NTOK / 8); cfg.blockDim = dim3(256);
        cfg.attrs = at; cfg.numAttrs = 1;
        cudaLaunchKernelEx(&cfg, k_ef, hidden, score_w);
    }
    {
        cudaLaunchConfig_t cfg = {};
        cfg.gridDim = dim3(NTOK / 256); cfg.blockDim = dim3(256);
        cfg.attrs = at; cfg.numAttrs = 1;
        cudaLaunchKernelEx(&cfg, k_scores, score_b, seq_len, gold);
    }
    {
        cudaLaunchConfig_t cfg = {};
        cfg.gridDim = dim3(16); cfg.blockDim = dim3(1024);
        cfg.attrs = at; cfg.numAttrs = 1;
        cudaLaunchKernelEx(&cfg, k_scan_count_final, out);
    }
}

// round 14
// speedup vs baseline: 1.1396x; 1.1396x over previous
#include <cuda_runtime.h>
#include <cuda_bf16.h>
#include <math.h>

#define Bb 32
#define Ss 512
#define Hh 1024
#define Mm 8
#define NTOK (Bb * Ss)       // 16384
#define NSPAN (NTOK * Mm)    // 131072
#define TOPK 4915            // int(0.3 * B * S)
#define NBIN 65536
#define NCOARSE 1024         // coarse bins: key >> 22 (== fine chunk of 64)
#define TIE_CAP 16384

// ---------------- device scratch ----------------
__device__ float g_query[Hh];
__device__ float g_e[NTOK];
__device__ float g_f[NTOK];
__device__ unsigned int g_keys[NSPAN];
__device__ int   g_hist16[NBIN];
__device__ int   g_coarse[NCOARSE];
__device__ unsigned char g_gbits[NTOK];   // bit l of byte t: span (t,l) valid&&gold
__device__ float g_sp_sum;
__device__ int   g_gold_cnt;
__device__ int   g_valid_cnt;
__device__ int   g_right;
__device__ int   g_tiecnt;
__device__ int   g_done;
__device__ int   g_tie[TIE_CAP];

__device__ __forceinline__ float warpReduceF(float v) {
    #pragma unroll
    for (int o = 16; o; o >>= 1) v += __shfl_xor_sync(0xffffffffu, v, o);
    return v;
}
__device__ __forceinline__ int warpReduceI(int v) {
    #pragma unroll
    for (int o = 16; o; o >>= 1) v += __shfl_xor_sync(0xffffffffu, v, o);
    return v;
}

// ---------------- kernel 1: query = w_in @ term_weight + b_in; init state ----------------
__global__ void k_query(const float* __restrict__ w_in,
                        const float* __restrict__ tw,
                        const float* __restrict__ b_in) {
    cudaTriggerProgrammaticLaunchCompletion();
    int r = blockIdx.x;
    if (r == 0 && threadIdx.x == 0) {
        g_sp_sum = 0.0f; g_gold_cnt = 0; g_valid_cnt = 0;
        g_right = 0; g_tiecnt = 0; g_done = 0;
    }
    const float4* wr = reinterpret_cast<const float4*>(w_in + (size_t)r * Hh);
    const float4* t4 = reinterpret_cast<const float4*>(tw);
    int i = threadIdx.x;
    float4 a = wr[i];
    float4 b = t4[i];
    float acc = a.x * b.x + a.y * b.y + a.z * b.z + a.w * b.w;

    __shared__ float sh[8];
    float v = warpReduceF(acc);
    if ((threadIdx.x & 31) == 0) sh[threadIdx.x >> 5] = v;
    __syncthreads();
    if (threadIdx.x < 8) {
        float x = sh[threadIdx.x];
        #pragma unroll
        for (int o = 4; o; o >>= 1) x += __shfl_xor_sync(0xffu, x, o);
        if (threadIdx.x == 0) g_query[r] = x + b_in[r];
    }
}

// ---------------- kernel 2: e/f dot products; also zeroes both hists ----------------
__global__ void k_ef(const float* __restrict__ hidden,
                     const float* __restrict__ score_w) {
    cudaTriggerProgrammaticLaunchCompletion();
    __shared__ float shq[Hh];
    __shared__ float shw[Hh];
    // independent prologue (overlaps k_query under PDL)
    int gid = blockIdx.x * blockDim.x + threadIdx.x;
    if (gid < NBIN) g_hist16[gid] = 0;
    if (gid < NCOARSE) g_coarse[gid] = 0;
    for (int i = threadIdx.x; i < Hh; i += blockDim.x) shw[i] = score_w[i];
    cudaGridDependencySynchronize();
    for (int i = threadIdx.x; i < Hh; i += blockDim.x) shq[i] = g_query[i];
    __syncthreads();

    int warp = threadIdx.x >> 5, lane = threadIdx.x & 31;
    int t = blockIdx.x * 8 + warp;
    const float4* hp = reinterpret_cast<const float4*>(hidden + (size_t)t * Hh);
    float e = 0.0f, f = 0.0f;
    #pragma unroll
    for (int c = 0; c < 8; c++) {
        int j = c * 32 + lane;
        float4 h = hp[j];
        int k = j * 4;
        e += h.x * shq[k] + h.y * shq[k + 1] + h.z * shq[k + 2] + h.w * shq[k + 3];
        f += h.x * shw[k] + h.y * shw[k + 1] + h.z * shw[k + 2] + h.w * shw[k + 3];
    }
    e = warpReduceF(e);
    f = warpReduceF(f);
    if (lane == 0) { g_e[t] = e; g_f[t] = f; }
}

// ---------------- kernel 3: scores, keys, gbits, loss, fine hist + smem-agg coarse hist ----
__global__ void k_scores(const float* __restrict__ score_b_p,
                         const int* __restrict__ seq_len,
                         const int* __restrict__ gold_mask) {
    cudaTriggerProgrammaticLaunchCompletion();
    __shared__ int sh_coarse[NCOARSE];     // 4KB per-block coarse histogram
    int t = blockIdx.x * blockDim.x + threadIdx.x;
    float sp_local = 0.0f;
    int gold_local = 0, valid_local = 0;

    // independent prologue: zero smem hist + pure-input loads (overlap k_ef under PDL)
    #pragma unroll
    for (int i = threadIdx.x; i < NCOARSE; i += 256) sh_coarse[i] = 0;
    int b = t >> 9, s = t & (Ss - 1);
    int L = seq_len[b];
    float sb = score_b_p[0];
    const int4* gm4 = reinterpret_cast<const int4*>(gold_mask + t * Mm);
    int4 gm0 = gm4[0], gm1 = gm4[1];
    int gm[8] = {gm0.x, gm0.y, gm0.z, gm0.w, gm1.x, gm1.y, gm1.z, gm1.w};

    cudaGridDependencySynchronize();   // wait for g_e/g_f + hist zeroing
    __syncthreads();                   // sh_coarse zeroed before use

    if (t < NTOK) {
        float m = -INFINITY, den = 0.0f, num = 0.0f;
        unsigned keys[8];
        unsigned char gb = 0;
        #pragma unroll
        for (int l = 0; l < Mm; l++) {
            int pos = s + l; if (pos > Ss - 1) pos = Ss - 1;
            float el = g_e[(b << 9) + pos];
            float fl = g_f[(b << 9) + pos];
            float mn = fmaxf(m, el);
            float sc = expf(m - mn);
            float we = expf(el - mn);
            den = den * sc + we;
            num = num * sc + we * fl;
            m = mn;
            float score = num / den + sb;

            unsigned key;
            if (s + l + 1 <= L) {
                unsigned u = __float_as_uint(score);
                key = u ^ ((u >> 31) ? 0xFFFFFFFFu : 0x80000000u);
                valid_local++;
                if (gm[l] == 0) {
                    gold_local++;
                    gb |= (unsigned char)(1u << l);
                    sp_local += fmaxf(-score, 0.0f) + log1pf(expf(-fabsf(score)));
                }
            } else {
                key = 0x007FFFFFu;  // flipped -inf
            }
            keys[l] = key;
            atomicAdd(&g_hist16[key >> 16], 1);        // fine: 65536 bins, spread
            atomicAdd(&sh_coarse[key >> 22], 1);       // coarse: shared, per-block
        }
        uint4* kp = reinterpret_cast<uint4*>(g_keys + t * Mm);
        kp[0] = make_uint4(keys[0], keys[1], keys[2], keys[3]);
        kp[1] = make_uint4(keys[4], keys[5], keys[6], keys[7]);
        g_gbits[t] = gb;
    }

    __shared__ float shf[8];
    __shared__ int shg[8], shv[8];
    float sp = warpReduceF(sp_local);
    int gd = warpReduceI(gold_local);
    int vd = warpReduceI(valid_local);
    if ((threadIdx.x & 31) == 0) {
        int w = threadIdx.x >> 5;
        shf[w] = sp; shg[w] = gd; shv[w] = vd;
    }
    __syncthreads();
    if (threadIdx.x == 0) {
        float S1 = 0.0f; int S2 = 0, S3 = 0;
        #pragma unroll
        for (int w = 0; w < 8; w++) { S1 += shf[w]; S2 += shg[w]; S3 += shv[w]; }
        atomicAdd(&g_sp_sum, S1);
        atomicAdd(&g_gold_cnt, S2);
        atomicAdd(&g_valid_cnt, S3);
    }

    // flush per-block coarse histogram (<=1024 spread atomics per block, skip zeros)
    #pragma unroll
    for (int i = threadIdx.x; i < NCOARSE; i += 256) {
        int v = sh_coarse[i];
        if (v) atomicAdd(&g_coarse[i], v);
    }
}

// ---------------- kernel 4: redundant per-block scan of coarse hist -> P,rem; count; final ----
// 16 blocks x 1024 threads. Each thread handles one token (8 spans).
__global__ void __launch_bounds__(1024, 1)
k_scan_count_final(float* __restrict__ out) {
    __shared__ int sch[NCOARSE];
    __shared__ int s_bins[64];
    __shared__ int s_bc, s_above;
    __shared__ int shc[32];
    __shared__ bool s_last;

    cudaGridDependencySynchronize();         // needs k_scores' hists + keys + gbits
    int tid = threadIdx.x;
    // ---- redundant suffix scan of coarse histogram (parallel across blocks) ----
    int csum = g_coarse[tid];
    sch[tid] = csum;
    __syncthreads();
    for (int off = 1; off < NCOARSE; off <<= 1) {
        int v = (tid + off < NCOARSE) ? sch[tid + off] : 0;
        __syncthreads();
        sch[tid] += v;
        __syncthreads();
    }
    int incl = sch[tid];
    int above = incl - csum;
    if (above < TOPK && incl >= TOPK) { s_bc = tid; s_above = above; }
    __syncthreads();
    int bc = s_bc;
    if (tid < 64) s_bins[tid] = g_hist16[bc * 64 + tid];   // fine bins of boundary coarse bin
    __syncthreads();
    if (tid == 0) {
        int cum = s_above;
        for (int bn = 63; bn >= 0; bn--) {
            int c = s_bins[bn];
            if (cum + c >= TOPK) {
                s_bc = bc * 64 + bn;        // P (16-bit prefix)
                s_above = TOPK - cum;       // rem
                break;
            }
            cum += c;
        }
    }
    __syncthreads();
    unsigned P = (unsigned)s_bc;
    int rem = s_above;

    // ---- vectorized count: token tg = gid (16*1024=16384 == NTOK) ----
    int tg = blockIdx.x * 1024 + tid;
    int gg = 0;
    {
        unsigned gb = g_gbits[tg];
        const uint4* kp = reinterpret_cast<const uint4*>(g_keys + tg * Mm);
        uint4 k0 = kp[0], k1 = kp[1];
        unsigned kk[8] = {k0.x, k0.y, k0.z, k0.w, k1.x, k1.y, k1.z, k1.w};
        #pragma unroll
        for (int l = 0; l < 8; l++) {
            unsigned top = kk[l] >> 16;
            if (top > P) {
                gg += (gb >> l) & 1;
            } else if (top == P) {
                int pos = atomicAdd(&g_tiecnt, 1);
                if (pos < TIE_CAP) g_tie[pos] = tg * Mm + l;
            }
        }
    }
    gg = warpReduceI(gg);
    if ((tid & 31) == 0) shc[tid >> 5] = gg;
    __syncthreads();
    if (tid == 0) {
        int S = 0;
        #pragma unroll
        for (int w = 0; w < 32; w++) S += shc[w];
        if (S) atomicAdd(&g_right, S);
        __threadfence();
        int d = atomicAdd(&g_done, 1);
        s_last = (d == (int)gridDim.x - 1);
    }
    __syncthreads();
    if (!s_last) return;

    // ---- final phase: only last block ----
    int n = g_tiecnt; if (n > TIE_CAP) n = TIE_CAP;
    __shared__ int s_g;
    if (tid == 0) s_g = 0;
    __syncthreads();

    int gtie = 0;
    for (int j = tid; j < n; j += 1024) {
        int ij = g_tie[j];
        unsigned kj = g_keys[ij];
        int rank = 0;
        for (int q = 0; q < n; q++) {
            int iq = g_tie[q];
            unsigned kq = g_keys[iq];
            if (kq > kj || (kq == kj && iq < ij)) rank++;
        }
        if (rank < rem) {
            if ((g_gbits[ij >> 3] >> (ij & 7)) & 1) gtie++;
        }
    }
    gtie = warpReduceI(gtie);
    if ((tid & 31) == 0 && gtie) atomicAdd(&s_g, gtie);
    __syncthreads();

    if (tid == 0) {
        int right = g_right + s_g;
        float nv = (float)g_valid_cnt;
        float loss = (g_sp_sum + 0.6931471805599453f * (float)(g_valid_cnt - g_gold_cnt)) / nv;
        out[0] = loss;
        out[1] = (float)right / (float)TOPK;
    }
}

// ---------------- launch (PDL on all dependent nodes) ----------------
extern "C" void kernel_launch(void* const* d_in, const int* in_sizes, int n_in,
                              void* d_out, int out_size) {
    const float* hidden  = (const float*)d_in[0];
    const float* tw      = (const float*)d_in[1];
    const float* w_in    = (const float*)d_in[2];
    const float* b_in    = (const float*)d_in[3];
    const float* score_w = (const float*)d_in[4];
    const float* score_b = (const float*)d_in[5];
    const int*   seq_len = (const int*)d_in[6];
    const int*   gold    = (const int*)d_in[7];
    float* out = (float*)d_out;

    cudaLaunchAttribute at[1];
    at[0].id = cudaLaunchAttributeProgrammaticStreamSerialization;
    at[0].val.programmaticStreamSerializationAllowed = 1;

    k_query<<<Hh, 256>>>(w_in, tw, b_in);
    {
        cudaLaunchConfig_t cfg = {};
        cfg.gridDim = dim3(NTOK / 8); cfg.blockDim = dim3(256);
        cfg.attrs = at; cfg.numAttrs = 1;
        cudaLaunchKernelEx(&cfg, k_ef, hidden, score_w);
    }
    {
        cudaLaunchConfig_t cfg = {};
        cfg.gridDim = dim3(NTOK / 256); cfg.blockDim = dim3(256);
        cfg.attrs = at; cfg.numAttrs = 1;
        cudaLaunchKernelEx(&cfg, k_scores, score_b, seq_len, gold);
    }
    {
        cudaLaunchConfig_t cfg = {};
        cfg.gridDim = dim3(16); cfg.blockDim = dim3(1024);
        cfg.attrs = at; cfg.numAttrs = 1;
        cudaLaunchKernelEx(&cfg, k_scan_count_final, out);
    }
}

// round 15
// speedup vs baseline: 1.1949x; 1.0485x over previous
#include <cuda_runtime.h>
#include <cuda_bf16.h>
#include <math.h>

#define Bb 32
#define Ss 512
#define Hh 1024
#define Mm 8
#define NTOK (Bb * Ss)       // 16384
#define NSPAN (NTOK * Mm)    // 131072
#define TOPK 4915            // int(0.3 * B * S)
#define NBIN 65536
#define NCOARSE 1024         // coarse bins: key >> 22 (== fine chunk of 64)
#define TIE_CAP 16384
#define SCF_BLOCKS 32        // k_scan_count_final grid

// ---------------- device scratch ----------------
__device__ float g_query[Hh];
__device__ float g_e[NTOK];
__device__ float g_f[NTOK];
__device__ unsigned int g_keys[NSPAN];
__device__ int   g_hist16[NBIN];
__device__ int   g_coarse[NCOARSE];
__device__ unsigned char g_gbits[NTOK];   // bit l of byte t: span (t,l) valid&&gold
__device__ float g_sp_sum;
__device__ int   g_gold_cnt;
__device__ int   g_valid_cnt;
__device__ int   g_right;
__device__ int   g_tiecnt;
__device__ int   g_done;
__device__ int   g_tie[TIE_CAP];

__device__ __forceinline__ float warpReduceF(float v) {
    #pragma unroll
    for (int o = 16; o; o >>= 1) v += __shfl_xor_sync(0xffffffffu, v, o);
    return v;
}
__device__ __forceinline__ int warpReduceI(int v) {
    #pragma unroll
    for (int o = 16; o; o >>= 1) v += __shfl_xor_sync(0xffffffffu, v, o);
    return v;
}

// ---------------- kernel 1: query = w_in @ term_weight + b_in; init state ----------------
__global__ void k_query(const float* __restrict__ w_in,
                        const float* __restrict__ tw,
                        const float* __restrict__ b_in) {
    cudaTriggerProgrammaticLaunchCompletion();
    int r = blockIdx.x;
    if (r == 0 && threadIdx.x == 0) {
        g_sp_sum = 0.0f; g_gold_cnt = 0; g_valid_cnt = 0;
        g_right = 0; g_tiecnt = 0; g_done = 0;
    }
    const float4* wr = reinterpret_cast<const float4*>(w_in + (size_t)r * Hh);
    const float4* t4 = reinterpret_cast<const float4*>(tw);
    int i = threadIdx.x;
    float4 a = wr[i];
    float4 b = t4[i];
    float acc = a.x * b.x + a.y * b.y + a.z * b.z + a.w * b.w;

    __shared__ float sh[8];
    float v = warpReduceF(acc);
    if ((threadIdx.x & 31) == 0) sh[threadIdx.x >> 5] = v;
    __syncthreads();
    if (threadIdx.x < 8) {
        float x = sh[threadIdx.x];
        #pragma unroll
        for (int o = 4; o; o >>= 1) x += __shfl_xor_sync(0xffu, x, o);
        if (threadIdx.x == 0) g_query[r] = x + b_in[r];
    }
}

// ---------------- kernel 2: e/f dot products; also zeroes both hists ----------------
__global__ void k_ef(const float* __restrict__ hidden,
                     const float* __restrict__ score_w) {
    cudaTriggerProgrammaticLaunchCompletion();
    __shared__ float shq[Hh];
    __shared__ float shw[Hh];
    // independent prologue (overlaps k_query under PDL)
    int gid = blockIdx.x * blockDim.x + threadIdx.x;
    if (gid < NBIN) g_hist16[gid] = 0;
    if (gid < NCOARSE) g_coarse[gid] = 0;
    for (int i = threadIdx.x; i < Hh; i += blockDim.x) shw[i] = score_w[i];
    cudaGridDependencySynchronize();
    for (int i = threadIdx.x; i < Hh; i += blockDim.x) shq[i] = g_query[i];
    __syncthreads();

    int warp = threadIdx.x >> 5, lane = threadIdx.x & 31;
    int t = blockIdx.x * 8 + warp;
    const float4* hp = reinterpret_cast<const float4*>(hidden + (size_t)t * Hh);
    float e = 0.0f, f = 0.0f;
    #pragma unroll
    for (int c = 0; c < 8; c++) {
        int j = c * 32 + lane;
        float4 h = hp[j];
        int k = j * 4;
        e += h.x * shq[k] + h.y * shq[k + 1] + h.z * shq[k + 2] + h.w * shq[k + 3];
        f += h.x * shw[k] + h.y * shw[k + 1] + h.z * shw[k + 2] + h.w * shw[k + 3];
    }
    e = warpReduceF(e);
    f = warpReduceF(f);
    if (lane == 0) { g_e[t] = e; g_f[t] = f; }
}

// ---------------- kernel 3: scores, keys, gbits, loss, fine hist + smem-agg coarse hist ----
__global__ void k_scores(const float* __restrict__ score_b_p,
                         const int* __restrict__ seq_len,
                         const int* __restrict__ gold_mask) {
    cudaTriggerProgrammaticLaunchCompletion();
    __shared__ int sh_coarse[NCOARSE];     // 4KB per-block coarse histogram
    int t = blockIdx.x * blockDim.x + threadIdx.x;
    float sp_local = 0.0f;
    int gold_local = 0, valid_local = 0;

    // independent prologue: zero smem hist + pure-input loads (overlap k_ef under PDL)
    #pragma unroll
    for (int i = threadIdx.x; i < NCOARSE; i += 256) sh_coarse[i] = 0;
    int b = t >> 9, s = t & (Ss - 1);
    int L = seq_len[b];
    float sb = score_b_p[0];
    const int4* gm4 = reinterpret_cast<const int4*>(gold_mask + t * Mm);
    int4 gm0 = gm4[0], gm1 = gm4[1];
    int gm[8] = {gm0.x, gm0.y, gm0.z, gm0.w, gm1.x, gm1.y, gm1.z, gm1.w};

    cudaGridDependencySynchronize();   // wait for g_e/g_f + hist zeroing
    __syncthreads();                   // sh_coarse zeroed before use

    if (t < NTOK) {
        float m = -INFINITY, den = 0.0f, num = 0.0f;
        unsigned keys[8];
        unsigned char gb = 0;
        #pragma unroll
        for (int l = 0; l < Mm; l++) {
            int pos = s + l; if (pos > Ss - 1) pos = Ss - 1;
            float el = g_e[(b << 9) + pos];
            float fl = g_f[(b << 9) + pos];
            float mn = fmaxf(m, el);
            float sc = expf(m - mn);
            float we = expf(el - mn);
            den = den * sc + we;
            num = num * sc + we * fl;
            m = mn;
            float score = num / den + sb;

            unsigned key;
            if (s + l + 1 <= L) {
                unsigned u = __float_as_uint(score);
                key = u ^ ((u >> 31) ? 0xFFFFFFFFu : 0x80000000u);
                valid_local++;
                if (gm[l] == 0) {
                    gold_local++;
                    gb |= (unsigned char)(1u << l);
                    sp_local += fmaxf(-score, 0.0f) + log1pf(expf(-fabsf(score)));
                }
            } else {
                key = 0x007FFFFFu;  // flipped -inf
            }
            keys[l] = key;
            atomicAdd(&g_hist16[key >> 16], 1);        // fine: 65536 bins, spread
            atomicAdd(&sh_coarse[key >> 22], 1);       // coarse: shared, per-block
        }
        uint4* kp = reinterpret_cast<uint4*>(g_keys + t * Mm);
        kp[0] = make_uint4(keys[0], keys[1], keys[2], keys[3]);
        kp[1] = make_uint4(keys[4], keys[5], keys[6], keys[7]);
        g_gbits[t] = gb;
    }

    __shared__ float shf[8];
    __shared__ int shg[8], shv[8];
    float sp = warpReduceF(sp_local);
    int gd = warpReduceI(gold_local);
    int vd = warpReduceI(valid_local);
    if ((threadIdx.x & 31) == 0) {
        int w = threadIdx.x >> 5;
        shf[w] = sp; shg[w] = gd; shv[w] = vd;
    }
    __syncthreads();
    if (threadIdx.x == 0) {
        float S1 = 0.0f; int S2 = 0, S3 = 0;
        #pragma unroll
        for (int w = 0; w < 8; w++) { S1 += shf[w]; S2 += shg[w]; S3 += shv[w]; }
        atomicAdd(&g_sp_sum, S1);
        atomicAdd(&g_gold_cnt, S2);
        atomicAdd(&g_valid_cnt, S3);
    }

    // flush per-block coarse histogram (<=1024 spread atomics per block, skip zeros)
    #pragma unroll
    for (int i = threadIdx.x; i < NCOARSE; i += 256) {
        int v = sh_coarse[i];
        if (v) atomicAdd(&g_coarse[i], v);
    }
}

// ---------------- kernel 4: shuffle-scan of coarse hist -> P,rem; wide count; last block final
// 32 blocks x 1024 threads. Each thread handles 4 spans (one uint4 + gbits nibble).
__global__ void __launch_bounds__(1024, 1)
k_scan_count_final(float* __restrict__ out) {
    __shared__ int s_wtot[32];     // per-warp totals
    __shared__ int s_wsuf[33];     // suffix over warp totals (s_wsuf[32]=0)
    __shared__ int s_bins[64];
    __shared__ int s_bc, s_above;
    __shared__ int shc[32];
    __shared__ bool s_last;

    cudaGridDependencySynchronize();         // needs k_scores' hists + keys + gbits
    int tid = threadIdx.x;
    int warp = tid >> 5, lane = tid & 31;

    // ---- hierarchical suffix scan of 1024 coarse bins (3 barriers total) ----
    int v = g_coarse[tid];
    // within-warp inclusive suffix (sum over lanes >= lane)
    int sfx = v;
    #pragma unroll
    for (int o = 1; o < 32; o <<= 1) {
        int x = __shfl_down_sync(0xffffffffu, sfx, o);
        if (lane + o < 32) sfx += x;
    }
    if (lane == 0) s_wtot[warp] = sfx;       // whole-warp total
    __syncthreads();
    if (warp == 0) {
        int wv = s_wtot[lane];
        int wsfx = wv;
        #pragma unroll
        for (int o = 1; o < 32; o <<= 1) {
            int x = __shfl_down_sync(0xffffffffu, wsfx, o);
            if (lane + o < 32) wsfx += x;
        }
        s_wsuf[lane] = wsfx;                 // suffix incl own warp
        if (lane == 0) s_wsuf[32] = 0;
    }
    __syncthreads();
    int incl = sfx + s_wsuf[warp + 1];       // suffix over bins >= tid
    int above = incl - v;
    if (above < TOPK && incl >= TOPK) { s_bc = tid; s_above = above; }
    __syncthreads();
    int bc = s_bc;
    if (tid < 64) s_bins[tid] = g_hist16[bc * 64 + tid];   // fine bins of boundary coarse bin
    __syncthreads();
    if (tid == 0) {
        int cum = s_above;
        for (int bn = 63; bn >= 0; bn--) {
            int c = s_bins[bn];
            if (cum + c >= TOPK) {
                s_bc = bc * 64 + bn;        // P (16-bit prefix)
                s_above = TOPK - cum;       // rem
                break;
            }
            cum += c;
        }
    }
    __syncthreads();
    unsigned P = (unsigned)s_bc;
    int rem = s_above;

    // ---- count: 4 spans per thread (32*1024*4 = 131072 == NSPAN) ----
    int gsp = (blockIdx.x * 1024 + tid) * 4;        // first span of this thread
    int gg = 0;
    {
        unsigned gb = g_gbits[gsp >> 3];
        unsigned nib = (gb >> (gsp & 7)) & 0xFu;     // 4 bits for spans gsp..gsp+3
        const uint4* kp = reinterpret_cast<const uint4*>(g_keys + gsp);
        uint4 k0 = kp[0];
        unsigned kk[4] = {k0.x, k0.y, k0.z, k0.w};
        #pragma unroll
        for (int l = 0; l < 4; l++) {
            unsigned top = kk[l] >> 16;
            if (top > P) {
                gg += (nib >> l) & 1;
            } else if (top == P) {
                int pos = atomicAdd(&g_tiecnt, 1);
                if (pos < TIE_CAP) g_tie[pos] = gsp + l;
            }
        }
    }
    gg = warpReduceI(gg);
    if (lane == 0) shc[warp] = gg;
    __syncthreads();
    if (tid == 0) {
        int S = 0;
        #pragma unroll
        for (int w = 0; w < 32; w++) S += shc[w];
        if (S) atomicAdd(&g_right, S);
        __threadfence();
        int d = atomicAdd(&g_done, 1);
        s_last = (d == (int)gridDim.x - 1);
    }
    __syncthreads();
    if (!s_last) return;

    // ---- final phase: only last block ----
    int n = g_tiecnt; if (n > TIE_CAP) n = TIE_CAP;
    __shared__ int s_g;
    if (tid == 0) s_g = 0;
    __syncthreads();

    int gtie = 0;
    for (int j = tid; j < n; j += 1024) {
        int ij = g_tie[j];
        unsigned kj = g_keys[ij];
        int rank = 0;
        for (int q = 0; q < n; q++) {
            int iq = g_tie[q];
            unsigned kq = g_keys[iq];
            if (kq > kj || (kq == kj && iq < ij)) rank++;
        }
        if (rank < rem) {
            if ((g_gbits[ij >> 3] >> (ij & 7)) & 1) gtie++;
        }
    }
    gtie = warpReduceI(gtie);
    if (lane == 0 && gtie) atomicAdd(&s_g, gtie);
    __syncthreads();

    if (tid == 0) {
        int right = g_right + s_g;
        float nv = (float)g_valid_cnt;
        float loss = (g_sp_sum + 0.6931471805599453f * (float)(g_valid_cnt - g_gold_cnt)) / nv;
        out[0] = loss;
        out[1] = (float)right / (float)TOPK;
    }
}

// ---------------- launch (PDL on all dependent nodes) ----------------
extern "C" void kernel_launch(void* const* d_in, const int* in_sizes, int n_in,
                              void* d_out, int out_size) {
    const float* hidden  = (const float*)d_in[0];
    const float* tw      = (const float*)d_in[1];
    const float* w_in    = (const float*)d_in[2];
    const float* b_in    = (const float*)d_in[3];
    const float* score_w = (const float*)d_in[4];
    const float* score_b = (const float*)d_in[5];
    const int*   seq_len = (const int*)d_in[6];
    const int*   gold    = (const int*)d_in[7];
    float* out = (float*)d_out;

    cudaLaunchAttribute at[1];
    at[0].id = cudaLaunchAttributeProgrammaticStreamSerialization;
    at[0].val.programmaticStreamSerializationAllowed = 1;

    k_query<<<Hh, 256>>>(w_in, tw, b_in);
    {
        cudaLaunchConfig_t cfg = {};
        cfg.gridDim = dim3(NTOK / 8); cfg.blockDim = dim3(256);
        cfg.attrs = at; cfg.numAttrs = 1;
        cudaLaunchKernelEx(&cfg, k_ef, hidden, score_w);
    }
    {
        cudaLaunchConfig_t cfg = {};
        cfg.gridDim = dim3(NTOK / 256); cfg.blockDim = dim3(256);
        cfg.attrs = at; cfg.numAttrs = 1;
        cudaLaunchKernelEx(&cfg, k_scores, score_b, seq_len, gold);
    }
    {
        cudaLaunchConfig_t cfg = {};
        cfg.gridDim = dim3(SCF_BLOCKS); cfg.blockDim = dim3(1024);
        cfg.attrs = at; cfg.numAttrs = 1;
        cudaLaunchKernelEx(&cfg, k_scan_count_final, out);
    }
}